// round 3
// baseline (speedup 1.0000x reference)
#include <cuda_runtime.h>

// SecGELU: out = (i>=0 ? x : 0) - table[min(|i>>6|, 4095)]
// where i = rint(x * 2^16) as int32 (exact ring semantics).
//
// Persistent grid-stride: table staged into SMEM ONCE per resident block
// (1184 blocks) instead of once per 4096-element tile (16384 blocks),
// removing the 1:1 table-staging overhead on the L1/LSU path.
// Streaming cache hints on the x/out stream (zero reuse).

#define SECGELU_TABLE_SIZE 4096
#define THREADS 256
#define V4_PER_THREAD 4                         // 16 elements per thread per tile
#define V4_PER_BLOCK (THREADS * V4_PER_THREAD)  // 1024 float4 = 4096 elems
#define GRID_BLOCKS (148 * 8)                   // fill 148 SMs at 2048 thr/SM

__device__ __forceinline__ float secgelu_one(float xi, const float* __restrict__ s_tab) {
    int i = __float2int_rn(xi * 65536.0f);   // X = round(x * 2^16), round-half-even
    int y = i >> 6;                          // floor division by 64 (exact for negatives)
    int a = (y >= 0) ? y : -y;               // |y|
    int c = min(a, SECGELU_TABLE_SIZE - 1);  // clamp
    float t = s_tab[c];
    return ((i >= 0) ? xi : 0.0f) - t;       // d*x - table[c]
}

__global__ void __launch_bounds__(THREADS)
secgelu_main_kernel(const float4* __restrict__ x4,
                    const float* __restrict__ table,
                    float4* __restrict__ out4,
                    long long n4) {
    __shared__ float s_tab[SECGELU_TABLE_SIZE];
    #pragma unroll
    for (int i = 0; i < SECGELU_TABLE_SIZE / THREADS; i++)
        s_tab[threadIdx.x + i * THREADS] = table[threadIdx.x + i * THREADS];
    __syncthreads();

    long long base = (long long)blockIdx.x * V4_PER_BLOCK + threadIdx.x;
    long long stride = (long long)gridDim.x * V4_PER_BLOCK;

    // Full tiles (no per-load bounds checks)
    for (; base + (V4_PER_THREAD - 1) * THREADS < n4; base += stride) {
        float4 v[V4_PER_THREAD];
        #pragma unroll
        for (int k = 0; k < V4_PER_THREAD; k++)
            v[k] = __ldcs(&x4[base + k * THREADS]);

        float4 r[V4_PER_THREAD];
        #pragma unroll
        for (int k = 0; k < V4_PER_THREAD; k++) {
            r[k].x = secgelu_one(v[k].x, s_tab);
            r[k].y = secgelu_one(v[k].y, s_tab);
            r[k].z = secgelu_one(v[k].z, s_tab);
            r[k].w = secgelu_one(v[k].w, s_tab);
        }

        #pragma unroll
        for (int k = 0; k < V4_PER_THREAD; k++)
            __stcs(&out4[base + k * THREADS], r[k]);
    }

    // Ragged last tile
    for (; base < n4; base += THREADS) {
        float4 v = __ldcs(&x4[base]);
        float4 r;
        r.x = secgelu_one(v.x, s_tab);
        r.y = secgelu_one(v.y, s_tab);
        r.z = secgelu_one(v.z, s_tab);
        r.w = secgelu_one(v.w, s_tab);
        __stcs(&out4[base], r);
    }
}

__global__ void __launch_bounds__(THREADS)
secgelu_tail_kernel(const float* __restrict__ x,
                    const float* __restrict__ table,
                    float* __restrict__ out,
                    long long start, long long n) {
    long long i = start + (long long)blockIdx.x * THREADS + threadIdx.x;
    if (i >= n) return;
    float xi = x[i];
    int ii = __float2int_rn(xi * 65536.0f);
    int y = ii >> 6;
    int a = (y >= 0) ? y : -y;
    int c = min(a, SECGELU_TABLE_SIZE - 1);
    out[i] = ((ii >= 0) ? xi : 0.0f) - table[c];
}

extern "C" void kernel_launch(void* const* d_in, const int* in_sizes, int n_in,
                              void* d_out, int out_size) {
    const float* x     = (const float*)d_in[0];
    const float* table = (const float*)d_in[1];
    float* out         = (float*)d_out;

    long long n  = (long long)in_sizes[0];
    long long n4 = n >> 2;

    if (n4 > 0) {
        int blocks = GRID_BLOCKS;
        long long max_useful = (n4 + V4_PER_BLOCK - 1) / V4_PER_BLOCK;
        if ((long long)blocks > max_useful) blocks = (int)max_useful;
        secgelu_main_kernel<<<blocks, THREADS>>>(
            (const float4*)x, table, (float4*)out, n4);
    }
    long long done = n4 << 2;
    long long n_tail = n - done;
    if (n_tail > 0) {
        long long tblocks = (n_tail + THREADS - 1) / THREADS;
        secgelu_tail_kernel<<<(int)tblocks, THREADS>>>(x, table, out, done, n);
    }
}

// round 4
// speedup vs baseline: 1.1196x; 1.1196x over previous
#include <cuda_runtime.h>

// SecGELU: out = (i>=0 ? x : 0) - table[min(|i>>6|, 4095)]
// where i = rint(x * 2^16) as int32 (exact ring semantics).
//
// Round-2 shape (one-shot blocks, exact grid, 32-bit addressing) with:
//  - float4-vectorized table staging (8x fewer staging instructions)
//  - 2 tiles per block (table staged half as often, 8192 blocks)

#define SECGELU_TABLE_SIZE 4096
#define THREADS 256
#define V4_PER_THREAD 4                         // 16 elements per thread per tile
#define V4_PER_TILE (THREADS * V4_PER_THREAD)   // 1024 float4 = 4096 elems
#define TILES_PER_BLOCK 2
#define V4_PER_BLOCK (V4_PER_TILE * TILES_PER_BLOCK)  // 2048 float4 = 8192 elems

__device__ __forceinline__ float secgelu_one(float xi, const float* __restrict__ s_tab) {
    int i = __float2int_rn(xi * 65536.0f);   // X = round(x * 2^16), round-half-even
    int y = i >> 6;                          // floor division by 64 (exact for negatives)
    int a = (y >= 0) ? y : -y;               // |y|
    int c = min(a, SECGELU_TABLE_SIZE - 1);  // clamp
    float t = s_tab[c];
    return ((i >= 0) ? xi : 0.0f) - t;       // d*x - table[c]
}

__device__ __forceinline__ void secgelu_tile(const float4* __restrict__ x4,
                                             float4* __restrict__ out4,
                                             int base,
                                             const float* __restrict__ s_tab) {
    float4 v[V4_PER_THREAD];
    #pragma unroll
    for (int k = 0; k < V4_PER_THREAD; k++)
        v[k] = x4[base + k * THREADS];

    float4 r[V4_PER_THREAD];
    #pragma unroll
    for (int k = 0; k < V4_PER_THREAD; k++) {
        r[k].x = secgelu_one(v[k].x, s_tab);
        r[k].y = secgelu_one(v[k].y, s_tab);
        r[k].z = secgelu_one(v[k].z, s_tab);
        r[k].w = secgelu_one(v[k].w, s_tab);
    }

    #pragma unroll
    for (int k = 0; k < V4_PER_THREAD; k++)
        out4[base + k * THREADS] = r[k];
}

__global__ void __launch_bounds__(THREADS)
secgelu_main_kernel(const float4* __restrict__ x4,
                    const float4* __restrict__ table4,
                    float4* __restrict__ out4) {
    __shared__ float s_tab[SECGELU_TABLE_SIZE];
    // Vectorized staging: 4096 floats = 1024 float4 = 4 per thread
    float4* s_tab4 = reinterpret_cast<float4*>(s_tab);
    #pragma unroll
    for (int i = 0; i < SECGELU_TABLE_SIZE / 4 / THREADS; i++)
        s_tab4[threadIdx.x + i * THREADS] = table4[threadIdx.x + i * THREADS];
    __syncthreads();

    int base = blockIdx.x * V4_PER_BLOCK + threadIdx.x;
    #pragma unroll
    for (int t = 0; t < TILES_PER_BLOCK; t++)
        secgelu_tile(x4, out4, base + t * V4_PER_TILE, s_tab);
}

__global__ void __launch_bounds__(THREADS)
secgelu_tail_kernel(const float* __restrict__ x,
                    const float* __restrict__ table,
                    float* __restrict__ out,
                    long long start, long long n) {
    long long i = start + (long long)blockIdx.x * THREADS + threadIdx.x;
    if (i >= n) return;
    float xi = x[i];
    int ii = __float2int_rn(xi * 65536.0f);
    int y = ii >> 6;
    int a = (y >= 0) ? y : -y;
    int c = min(a, SECGELU_TABLE_SIZE - 1);
    out[i] = ((ii >= 0) ? xi : 0.0f) - table[c];
}

extern "C" void kernel_launch(void* const* d_in, const int* in_sizes, int n_in,
                              void* d_out, int out_size) {
    const float* x     = (const float*)d_in[0];
    const float* table = (const float*)d_in[1];
    float* out         = (float*)d_out;

    long long n = (long long)in_sizes[0];
    long long elems_per_block = (long long)V4_PER_BLOCK * 4;  // 8192
    long long nblocks = n / elems_per_block;

    if (nblocks > 0) {
        secgelu_main_kernel<<<(int)nblocks, THREADS>>>(
            (const float4*)x, (const float4*)table, (float4*)out);
    }
    long long done = nblocks * elems_per_block;
    long long n_tail = n - done;
    if (n_tail > 0) {
        long long tblocks = (n_tail + THREADS - 1) / THREADS;
        secgelu_tail_kernel<<<(int)tblocks, THREADS>>>(x, table, out, done, n);
    }
}